// round 4
// baseline (speedup 1.0000x reference)
#include <cuda_runtime.h>

#define D 128
#define H 8
#define MAXN 50000
#define MAXE 800000

// ---- scratch (static device globals; no allocation allowed) ----
__device__ float g_q[MAXN * D];
__device__ float g_k[MAXN * D];
__device__ float g_v[MAXN * D];
__device__ float g_agg[MAXN * D];
__device__ float g_scores[(size_t)MAXE * H];
__device__ float g_smax[MAXN * H];
__device__ float g_denom[MAXN * H];
__device__ float g_cnt[MAXN];

// ============================================================================
// GEMM: C[m, j] = scale(m) * sum_k A[m,k] * W[j,k] + bias[j]
//   A: [M, 128] row-major, W: [128, 128] row-major (used transposed)
//   cnt != nullptr -> scale(m) = 1 / max(cnt[m], 1)   (for the O projection)
// Tiling: BM=128, BN=128, BK=8, 256 threads, 8x8 register tile per thread.
// ============================================================================
__global__ __launch_bounds__(256) void gemm_bias_kernel(
    const float* __restrict__ A, const float* __restrict__ W,
    const float* __restrict__ bias, const float* __restrict__ cnt,
    float* __restrict__ C, int M)
{
    __shared__ float sA[8][132];   // +4 pad to dodge the 512-float stride conflict
    __shared__ float sW[8][132];

    const int tid = threadIdx.x;
    const int bm  = blockIdx.x * 128;
    const int tx  = tid & 15;     // -> output col group
    const int ty  = tid >> 4;     // -> output row group
    const int lr  = tid >> 1;     // load row within tile (0..127)
    const int lc  = (tid & 1) * 4;// load col within 8-wide K slab (0 or 4)

    float acc[8][8];
#pragma unroll
    for (int i = 0; i < 8; i++)
#pragma unroll
        for (int j = 0; j < 8; j++) acc[i][j] = 0.0f;

    for (int k0 = 0; k0 < D; k0 += 8) {
        const int grow = bm + lr;
        float4 av = make_float4(0.f, 0.f, 0.f, 0.f);
        if (grow < M) av = *(const float4*)(A + (size_t)grow * D + k0 + lc);
        sA[lc + 0][lr] = av.x; sA[lc + 1][lr] = av.y;
        sA[lc + 2][lr] = av.z; sA[lc + 3][lr] = av.w;

        const float4 wv = *(const float4*)(W + (size_t)lr * D + k0 + lc);
        sW[lc + 0][lr] = wv.x; sW[lc + 1][lr] = wv.y;
        sW[lc + 2][lr] = wv.z; sW[lc + 3][lr] = wv.w;
        __syncthreads();

#pragma unroll
        for (int kk = 0; kk < 8; kk++) {
            float a[8], w[8];
#pragma unroll
            for (int i = 0; i < 8; i++) a[i] = sA[kk][ty + i * 16];
#pragma unroll
            for (int j = 0; j < 8; j++) w[j] = sW[kk][tx + j * 16];
#pragma unroll
            for (int i = 0; i < 8; i++)
#pragma unroll
                for (int j = 0; j < 8; j++)
                    acc[i][j] = fmaf(a[i], w[j], acc[i][j]);
        }
        __syncthreads();
    }

#pragma unroll
    for (int i = 0; i < 8; i++) {
        const int row = bm + ty + i * 16;
        if (row >= M) continue;
        float s = 1.0f;
        if (cnt) s = 1.0f / fmaxf(cnt[row], 1.0f);
#pragma unroll
        for (int j = 0; j < 8; j++) {
            const int col = tx + j * 16;
            C[(size_t)row * D + col] = acc[i][j] * s + bias[col];
        }
    }
}

// ============================================================================
// Edge pass 1: one warp per edge.
//   scores[e,h] = dot(q[c,h,:], k[r,h,:]) / 4
//   smax[c,h]  = max over edges (via int-atomicMax; init 0 covers max(.,0))
//   cnt[c]    += 1
// Lane l holds float4 of dim [4l, 4l+4); head h = l >> 2.
// edge_index is int32 (JAX x64 disabled): int2 per edge {r, c}.
// ============================================================================
__global__ __launch_bounds__(256) void edge_scores_kernel(
    const int* __restrict__ ei, int E)
{
    const int e    = blockIdx.x * 8 + (threadIdx.x >> 5);
    const int lane = threadIdx.x & 31;
    if (e >= E) return;

    int r = 0, c = 0;
    if (lane == 0) {
        const int2 rc = ((const int2*)ei)[e];
        r = rc.x; c = rc.y;
    }
    r = __shfl_sync(0xffffffffu, r, 0);
    c = __shfl_sync(0xffffffffu, c, 0);

    const float4 qv = ((const float4*)g_q)[c * 32 + lane];
    const float4 kv = ((const float4*)g_k)[r * 32 + lane];
    float s = qv.x * kv.x + qv.y * kv.y + qv.z * kv.z + qv.w * kv.w;
    s += __shfl_xor_sync(0xffffffffu, s, 1);
    s += __shfl_xor_sync(0xffffffffu, s, 2);   // reduced within each group of 4
    s *= 0.25f;                                 // / sqrt(HD=16)

    if ((lane & 3) == 0) {
        const int h = lane >> 2;
        g_scores[(size_t)e * H + h] = s;
        if (s > 0.0f)
            atomicMax((int*)&g_smax[c * H + h], __float_as_int(s));
    }
    if (lane == 0) atomicAdd(&g_cnt[c], 1.0f);
}

// ============================================================================
// Edge pass 2: one thread per (edge, head).
//   denom[c,h] += exp(scores[e,h] - smax[c,h])
// ============================================================================
__global__ __launch_bounds__(256) void edge_denom_kernel(
    const int* __restrict__ ei, int E)
{
    const int i = blockIdx.x * blockDim.x + threadIdx.x;
    if (i >= E * H) return;
    const int e = i >> 3;
    const int h = i & 7;
    const int c = ei[2 * e + 1];
    const float ex = __expf(g_scores[i] - g_smax[c * H + h]);
    atomicAdd(&g_denom[c * H + h], ex);
}

// ============================================================================
// Edge pass 3: one warp per edge.
//   attn = exp(sc - mx) / (denom + exp(-mx))
//   agg[c,:] += attn[h] * v[r,:]   via red.global.add.v4.f32 (16B vector RED)
// ============================================================================
__global__ __launch_bounds__(256) void edge_agg_kernel(
    const int* __restrict__ ei, int E)
{
    const int e    = blockIdx.x * 8 + (threadIdx.x >> 5);
    const int lane = threadIdx.x & 31;
    if (e >= E) return;

    int r = 0, c = 0;
    if (lane == 0) {
        const int2 rc = ((const int2*)ei)[e];
        r = rc.x; c = rc.y;
    }
    r = __shfl_sync(0xffffffffu, r, 0);
    c = __shfl_sync(0xffffffffu, c, 0);

    const int h = lane >> 2;
    const float sc = g_scores[(size_t)e * H + h];
    const float mx = g_smax[c * H + h];
    const float dn = g_denom[c * H + h];
    const float a  = __expf(sc - mx) / (dn + __expf(-mx));

    const float4 vv = ((const float4*)g_v)[r * 32 + lane];
    float* dst = g_agg + (size_t)c * D + lane * 4;
    asm volatile("red.global.add.v4.f32 [%0], {%1, %2, %3, %4};"
                 :: "l"(dst), "f"(a * vv.x), "f"(a * vv.y),
                    "f"(a * vv.z), "f"(a * vv.w)
                 : "memory");
}

// ============================================================================
// Launch
// ============================================================================
extern "C" void kernel_launch(void* const* d_in, const int* in_sizes, int n_in,
                              void* d_out, int out_size)
{
    const float* feats = (const float*)d_in[0];
    const int*   ei    = (const int*)d_in[1];
    const float* Wq = (const float*)d_in[2]; const float* bq = (const float*)d_in[3];
    const float* Wk = (const float*)d_in[4]; const float* bk = (const float*)d_in[5];
    const float* Wv = (const float*)d_in[6]; const float* bv = (const float*)d_in[7];
    const float* Wo = (const float*)d_in[8]; const float* bo = (const float*)d_in[9];
    float* out = (float*)d_out;

    const int N = in_sizes[0] / D;
    const int E = in_sizes[1] / 2;

    float *q, *k, *v, *agg, *smax, *denom, *cnt;
    cudaGetSymbolAddress((void**)&q,     g_q);
    cudaGetSymbolAddress((void**)&k,     g_k);
    cudaGetSymbolAddress((void**)&v,     g_v);
    cudaGetSymbolAddress((void**)&agg,   g_agg);
    cudaGetSymbolAddress((void**)&smax,  g_smax);
    cudaGetSymbolAddress((void**)&denom, g_denom);
    cudaGetSymbolAddress((void**)&cnt,   g_cnt);

    cudaMemsetAsync(smax,  0, (size_t)N * H * sizeof(float));
    cudaMemsetAsync(denom, 0, (size_t)N * H * sizeof(float));
    cudaMemsetAsync(cnt,   0, (size_t)N * sizeof(float));
    cudaMemsetAsync(agg,   0, (size_t)N * D * sizeof(float));

    const int gblocks = (N + 127) / 128;
    gemm_bias_kernel<<<gblocks, 256>>>(feats, Wq, bq, nullptr, q, N);
    gemm_bias_kernel<<<gblocks, 256>>>(feats, Wk, bk, nullptr, k, N);
    gemm_bias_kernel<<<gblocks, 256>>>(feats, Wv, bv, nullptr, v, N);

    edge_scores_kernel<<<(E + 7) / 8, 256>>>(ei, E);
    edge_denom_kernel<<<(E * H + 255) / 256, 256>>>(ei, E);
    edge_agg_kernel<<<(E + 7) / 8, 256>>>(ei, E);

    gemm_bias_kernel<<<gblocks, 256>>>(agg, Wo, bo, cnt, out, N);
}

// round 5
// speedup vs baseline: 1.4065x; 1.4065x over previous
#include <cuda_runtime.h>

#define D 128
#define H 8
#define MAXN 50000
#define MAXE 800000

// ---- scratch (static device globals; no allocation allowed) ----
__device__ float g_q[MAXN * D];
__device__ float g_k[MAXN * D];
__device__ float g_v[MAXN * D];
__device__ float g_agg[MAXN * D];
__device__ float g_scores[(size_t)MAXE * H];   // scores at CSR positions
__device__ int   g_deg[MAXN];
__device__ int   g_rowptr[MAXN + 1];
__device__ int   g_cursor[MAXN];
__device__ int   g_src[MAXE];                  // source node r per CSR slot

// ============================================================================
// Packed-f32x2 helpers (FFMA2: 2 FMAs per issue slot on sm_103a)
// ============================================================================
__device__ __forceinline__ void fma2(unsigned long long& d,
                                     unsigned long long a,
                                     unsigned long long b) {
    asm("fma.rn.f32x2 %0, %1, %2, %0;" : "+l"(d) : "l"(a), "l"(b));
}
__device__ __forceinline__ unsigned long long pack2(float x) {
    unsigned long long r;
    asm("mov.b64 %0, {%1, %1};" : "=l"(r) : "f"(x));
    return r;
}
__device__ __forceinline__ void unpack2(unsigned long long d, float& lo, float& hi) {
    asm("mov.b64 {%0, %1}, %2;" : "=f"(lo), "=f"(hi) : "l"(d));
}

// ============================================================================
// GEMM: C[m, j] = sum_k A[m,k] * W[j,k] + bias[j]
// BM=128, BN=128, BK=16, 256 threads. Per thread: 8 rows x 4 col-pairs,
// inner product via fma.rn.f32x2 (32 FFMA2 = 64 FMAs per kk step).
// ============================================================================
__global__ __launch_bounds__(256) void gemm_bias_kernel(
    const float* __restrict__ A, const float* __restrict__ W,
    const float* __restrict__ bias, float* __restrict__ C, int M)
{
    __shared__ __align__(16) float sA[16][132];
    __shared__ __align__(16) float sW[16][132];

    const int tid = threadIdx.x;
    const int bm  = blockIdx.x * 128;
    const int tx  = tid & 15;      // col-pair group: cols 2*tx + 32*jp (+0/+1)
    const int ty  = tid >> 4;      // row group: rows ty + 16*i
    const int lr  = tid >> 1;      // load row 0..127
    const int lc  = (tid & 1) * 8; // load col offset within 16-wide K slab

    unsigned long long acc[8][4];
#pragma unroll
    for (int i = 0; i < 8; i++)
#pragma unroll
        for (int j = 0; j < 4; j++) acc[i][j] = 0ull;

    for (int k0 = 0; k0 < D; k0 += 16) {
        const int grow = bm + lr;
        float4 a0 = make_float4(0.f, 0.f, 0.f, 0.f), a1 = a0;
        if (grow < M) {
            a0 = *(const float4*)(A + (size_t)grow * D + k0 + lc);
            a1 = *(const float4*)(A + (size_t)grow * D + k0 + lc + 4);
        }
        sA[lc + 0][lr] = a0.x; sA[lc + 1][lr] = a0.y;
        sA[lc + 2][lr] = a0.z; sA[lc + 3][lr] = a0.w;
        sA[lc + 4][lr] = a1.x; sA[lc + 5][lr] = a1.y;
        sA[lc + 6][lr] = a1.z; sA[lc + 7][lr] = a1.w;

        const float4 w0 = *(const float4*)(W + (size_t)lr * D + k0 + lc);
        const float4 w1 = *(const float4*)(W + (size_t)lr * D + k0 + lc + 4);
        sW[lc + 0][lr] = w0.x; sW[lc + 1][lr] = w0.y;
        sW[lc + 2][lr] = w0.z; sW[lc + 3][lr] = w0.w;
        sW[lc + 4][lr] = w1.x; sW[lc + 5][lr] = w1.y;
        sW[lc + 6][lr] = w1.z; sW[lc + 7][lr] = w1.w;
        __syncthreads();

#pragma unroll
        for (int kk = 0; kk < 16; kk++) {
            unsigned long long ad[8], wd[4];
#pragma unroll
            for (int i = 0; i < 8; i++) ad[i] = pack2(sA[kk][ty + i * 16]);
#pragma unroll
            for (int jp = 0; jp < 4; jp++)
                wd[jp] = *(const unsigned long long*)&sW[kk][2 * tx + 32 * jp];
#pragma unroll
            for (int i = 0; i < 8; i++)
#pragma unroll
                for (int jp = 0; jp < 4; jp++)
                    fma2(acc[i][jp], ad[i], wd[jp]);
        }
        __syncthreads();
    }

    float2 bv[4];
#pragma unroll
    for (int jp = 0; jp < 4; jp++)
        bv[jp] = *(const float2*)&bias[2 * tx + 32 * jp];

#pragma unroll
    for (int i = 0; i < 8; i++) {
        const int row = bm + ty + i * 16;
        if (row >= M) continue;
#pragma unroll
        for (int jp = 0; jp < 4; jp++) {
            float lo, hi;
            unpack2(acc[i][jp], lo, hi);
            *(float2*)&C[(size_t)row * D + 2 * tx + 32 * jp] =
                make_float2(lo + bv[jp].x, hi + bv[jp].y);
        }
    }
}

// ============================================================================
// CSR build: histogram -> exclusive scan -> scatter (by destination c)
// ============================================================================
__global__ __launch_bounds__(256) void deg_kernel(const int* __restrict__ ei, int E)
{
    const int e = blockIdx.x * blockDim.x + threadIdx.x;
    if (e >= E) return;
    const int2 rc = ((const int2*)ei)[e];
    atomicAdd(&g_deg[rc.y], 1);
}

__global__ __launch_bounds__(1024) void scan_kernel(int N, int E)
{
    __shared__ int ssum[1024];
    __shared__ int s_carry;
    const int tid = threadIdx.x;
    if (tid == 0) s_carry = 0;
    __syncthreads();

    for (int base = 0; base < N; base += 8192) {
        const int idx0 = base + tid * 8;
        int vals[8], tsum = 0;
#pragma unroll
        for (int t = 0; t < 8; t++) {
            vals[t] = (idx0 + t < N) ? g_deg[idx0 + t] : 0;
            tsum += vals[t];
        }
        const int carry_old = s_carry;
        ssum[tid] = tsum;
        __syncthreads();
        for (int off = 1; off < 1024; off <<= 1) {
            int v = (tid >= off) ? ssum[tid - off] : 0;
            __syncthreads();
            ssum[tid] += v;
            __syncthreads();
        }
        int run = carry_old + ssum[tid] - tsum;  // exclusive prefix of first elem
#pragma unroll
        for (int t = 0; t < 8; t++) {
            if (idx0 + t < N) g_rowptr[idx0 + t] = run;
            run += vals[t];
        }
        __syncthreads();
        if (tid == 0) s_carry = carry_old + ssum[1023];
        __syncthreads();
    }
    if (tid == 0) g_rowptr[N] = E;
}

__global__ __launch_bounds__(256) void scatter_kernel(const int* __restrict__ ei, int E)
{
    const int e = blockIdx.x * blockDim.x + threadIdx.x;
    if (e >= E) return;
    const int2 rc = ((const int2*)ei)[e];
    const int pos = g_rowptr[rc.y] + atomicAdd(&g_cursor[rc.y], 1);
    g_src[pos] = rc.x;
}

// ============================================================================
// Fused per-node attention: one warp per destination node.
// Lane l holds dims [4l, 4l+4); head of lane = l >> 2.
//   loop1: scores + running max (store scores at CSR slots)
//   loop2: denom per head (lane layout: edge = j + (lane>>3), head = lane&7)
//   loop3: agg += attn * v[r];  write agg / max(deg,1)
// ============================================================================
__global__ __launch_bounds__(256) void node_attn_kernel(int N)
{
    const int nid  = blockIdx.x * 8 + (threadIdx.x >> 5);
    const int lane = threadIdx.x & 31;
    if (nid >= N) return;

    const int start = g_rowptr[nid];
    const int end   = g_rowptr[nid + 1];
    const int deg   = end - start;

    const float4 qv = ((const float4*)g_q)[nid * 32 + lane];
    float mymax = -1e30f;

    // ---- loop1: scores + max ----
#pragma unroll 2
    for (int j = start; j < end; j++) {
        const int r = g_src[j];
        const float4 kv = ((const float4*)g_k)[r * 32 + lane];
        float s = qv.x * kv.x + qv.y * kv.y + qv.z * kv.z + qv.w * kv.w;
        s += __shfl_xor_sync(0xffffffffu, s, 1);
        s += __shfl_xor_sync(0xffffffffu, s, 2);
        s *= 0.25f;                               // / sqrt(16)
        if ((lane & 3) == 0) {
            g_scores[(size_t)j * H + (lane >> 2)] = s;
            mymax = fmaxf(mymax, s);
        }
    }
    __syncwarp();

    // per-head clamped max, broadcast to both lane layouts
    const float mx3 = fmaxf(__shfl_sync(0xffffffffu, mymax, lane & ~3), 0.0f); // head=lane>>2
    const float mx2 = fmaxf(__shfl_sync(0xffffffffu, mymax, (lane & 7) * 4), 0.0f); // head=lane&7

    // ---- loop2: denom ----
    float dsum = 0.0f;
    for (int jb = start; jb < end; jb += 4) {
        const int j = jb + (lane >> 3);
        if (j < end)
            dsum += __expf(g_scores[(size_t)j * H + (lane & 7)] - mx2);
    }
    dsum += __shfl_xor_sync(0xffffffffu, dsum, 8);
    dsum += __shfl_xor_sync(0xffffffffu, dsum, 16);
    const float invd_my = 1.0f / (dsum + __expf(-mx2));     // head = lane&7
    const float invd = __shfl_sync(0xffffffffu, invd_my, lane >> 2); // head = lane>>2

    // ---- loop3: aggregate ----
    float4 acc = make_float4(0.f, 0.f, 0.f, 0.f);
#pragma unroll 2
    for (int j = start; j < end; j++) {
        const int r = g_src[j];
        float scv = 0.0f;
        if (lane < 8) scv = g_scores[(size_t)j * H + lane];
        const float sc = __shfl_sync(0xffffffffu, scv, lane >> 2);
        const float a  = __expf(sc - mx3) * invd;
        const float4 vv = ((const float4*)g_v)[r * 32 + lane];
        acc.x = fmaf(a, vv.x, acc.x);
        acc.y = fmaf(a, vv.y, acc.y);
        acc.z = fmaf(a, vv.z, acc.z);
        acc.w = fmaf(a, vv.w, acc.w);
    }

    const float inv_cnt = 1.0f / (float)max(deg, 1);
    acc.x *= inv_cnt; acc.y *= inv_cnt; acc.z *= inv_cnt; acc.w *= inv_cnt;
    ((float4*)g_agg)[nid * 32 + lane] = acc;
}

// ============================================================================
// Launch
// ============================================================================
extern "C" void kernel_launch(void* const* d_in, const int* in_sizes, int n_in,
                              void* d_out, int out_size)
{
    const float* feats = (const float*)d_in[0];
    const int*   ei    = (const int*)d_in[1];
    const float* Wq = (const float*)d_in[2]; const float* bq = (const float*)d_in[3];
    const float* Wk = (const float*)d_in[4]; const float* bk = (const float*)d_in[5];
    const float* Wv = (const float*)d_in[6]; const float* bv = (const float*)d_in[7];
    const float* Wo = (const float*)d_in[8]; const float* bo = (const float*)d_in[9];
    float* out = (float*)d_out;

    const int N = in_sizes[0] / D;
    const int E = in_sizes[1] / 2;

    float *q, *k, *v, *agg;
    int *deg, *cursor;
    cudaGetSymbolAddress((void**)&q,      g_q);
    cudaGetSymbolAddress((void**)&k,      g_k);
    cudaGetSymbolAddress((void**)&v,      g_v);
    cudaGetSymbolAddress((void**)&agg,    g_agg);
    cudaGetSymbolAddress((void**)&deg,    g_deg);
    cudaGetSymbolAddress((void**)&cursor, g_cursor);

    cudaMemsetAsync(deg,    0, (size_t)N * sizeof(int));
    cudaMemsetAsync(cursor, 0, (size_t)N * sizeof(int));

    const int gblocks = (N + 127) / 128;
    gemm_bias_kernel<<<gblocks, 256>>>(feats, Wq, bq, q, N);
    gemm_bias_kernel<<<gblocks, 256>>>(feats, Wk, bk, k, N);
    gemm_bias_kernel<<<gblocks, 256>>>(feats, Wv, bv, v, N);

    deg_kernel<<<(E + 255) / 256, 256>>>(ei, E);
    scan_kernel<<<1, 1024>>>(N, E);
    scatter_kernel<<<(E + 255) / 256, 256>>>(ei, E);

    node_attn_kernel<<<(N + 7) / 8, 256>>>(N);

    gemm_bias_kernel<<<gblocks, 256>>>(agg, Wo, bo, out, N);
}

// round 7
// speedup vs baseline: 1.4244x; 1.0127x over previous
#include <cuda_runtime.h>

#define D 128
#define H 8
#define MAXN 50000
#define MAXE 800000

// ---- scratch (static device globals; no allocation allowed) ----
__device__ float g_q[MAXN * D];
__device__ float g_k[MAXN * D];
__device__ float g_v[MAXN * D];
__device__ float g_agg[MAXN * D];
__device__ int   g_deg[MAXN];
__device__ int   g_rowptr[MAXN + 1];
__device__ int   g_cursor[MAXN];
__device__ int   g_src[MAXE];                  // source node r per CSR slot

// ============================================================================
// Packed-f32x2 helpers (FFMA2: 2 FMAs per issue slot on sm_103a)
// ============================================================================
__device__ __forceinline__ void fma2(unsigned long long& d,
                                     unsigned long long a,
                                     unsigned long long b) {
    asm("fma.rn.f32x2 %0, %1, %2, %0;" : "+l"(d) : "l"(a), "l"(b));
}
__device__ __forceinline__ unsigned long long pack2(float x) {
    unsigned long long r;
    asm("mov.b64 %0, {%1, %1};" : "=l"(r) : "f"(x));
    return r;
}
__device__ __forceinline__ void unpack2(unsigned long long d, float& lo, float& hi) {
    asm("mov.b64 {%0, %1}, %2;" : "=f"(lo), "=f"(hi) : "l"(d));
}

// ============================================================================
// GEMM: C[m, j] = sum_k A[m,k] * W[j,k] + bias[j]
// BM=128, BN=128, BK=16, 256 threads, FFMA2 inner product.
// ============================================================================
__global__ __launch_bounds__(256) void gemm_bias_kernel(
    const float* __restrict__ A, const float* __restrict__ W,
    const float* __restrict__ bias, float* __restrict__ C, int M)
{
    __shared__ __align__(16) float sA[16][132];
    __shared__ __align__(16) float sW[16][132];

    const int tid = threadIdx.x;
    const int bm  = blockIdx.x * 128;
    const int tx  = tid & 15;      // col-pair group: cols 2*tx + 32*jp (+0/+1)
    const int ty  = tid >> 4;      // row group: rows ty + 16*i
    const int lr  = tid >> 1;      // load row 0..127
    const int lc  = (tid & 1) * 8; // load col offset within 16-wide K slab

    unsigned long long acc[8][4];
#pragma unroll
    for (int i = 0; i < 8; i++)
#pragma unroll
        for (int j = 0; j < 4; j++) acc[i][j] = 0ull;

    for (int k0 = 0; k0 < D; k0 += 16) {
        const int grow = bm + lr;
        float4 a0 = make_float4(0.f, 0.f, 0.f, 0.f), a1 = a0;
        if (grow < M) {
            a0 = *(const float4*)(A + (size_t)grow * D + k0 + lc);
            a1 = *(const float4*)(A + (size_t)grow * D + k0 + lc + 4);
        }
        sA[lc + 0][lr] = a0.x; sA[lc + 1][lr] = a0.y;
        sA[lc + 2][lr] = a0.z; sA[lc + 3][lr] = a0.w;
        sA[lc + 4][lr] = a1.x; sA[lc + 5][lr] = a1.y;
        sA[lc + 6][lr] = a1.z; sA[lc + 7][lr] = a1.w;

        const float4 w0 = *(const float4*)(W + (size_t)lr * D + k0 + lc);
        const float4 w1 = *(const float4*)(W + (size_t)lr * D + k0 + lc + 4);
        sW[lc + 0][lr] = w0.x; sW[lc + 1][lr] = w0.y;
        sW[lc + 2][lr] = w0.z; sW[lc + 3][lr] = w0.w;
        sW[lc + 4][lr] = w1.x; sW[lc + 5][lr] = w1.y;
        sW[lc + 6][lr] = w1.z; sW[lc + 7][lr] = w1.w;
        __syncthreads();

#pragma unroll
        for (int kk = 0; kk < 16; kk++) {
            unsigned long long ad[8], wd[4];
#pragma unroll
            for (int i = 0; i < 8; i++) ad[i] = pack2(sA[kk][ty + i * 16]);
#pragma unroll
            for (int jp = 0; jp < 4; jp++)
                wd[jp] = *(const unsigned long long*)&sW[kk][2 * tx + 32 * jp];
#pragma unroll
            for (int i = 0; i < 8; i++)
#pragma unroll
                for (int jp = 0; jp < 4; jp++)
                    fma2(acc[i][jp], ad[i], wd[jp]);
        }
        __syncthreads();
    }

    float2 bv[4];
#pragma unroll
    for (int jp = 0; jp < 4; jp++)
        bv[jp] = *(const float2*)&bias[2 * tx + 32 * jp];

#pragma unroll
    for (int i = 0; i < 8; i++) {
        const int row = bm + ty + i * 16;
        if (row >= M) continue;
#pragma unroll
        for (int jp = 0; jp < 4; jp++) {
            float lo, hi;
            unpack2(acc[i][jp], lo, hi);
            *(float2*)&C[(size_t)row * D + 2 * tx + 32 * jp] =
                make_float2(lo + bv[jp].x, hi + bv[jp].y);
        }
    }
}

// ============================================================================
// CSR build: histogram -> scan (writes rowptr AND seeds cursor) -> scatter
// ============================================================================
__global__ __launch_bounds__(256) void deg_kernel(const int* __restrict__ ei, int E)
{
    const int i = blockIdx.x * blockDim.x + threadIdx.x;   // 2 edges per thread
    const int e0 = i * 2;
    if (e0 >= E) return;
    const int4 p = ((const int4*)ei)[i];   // {r0,c0,r1,c1}
    atomicAdd(&g_deg[p.y], 1);
    if (e0 + 1 < E) atomicAdd(&g_deg[p.w], 1);
}

__global__ __launch_bounds__(1024) void scan_kernel(int N, int E)
{
    __shared__ int ssum[1024];
    __shared__ int s_carry;
    const int tid = threadIdx.x;
    if (tid == 0) s_carry = 0;
    __syncthreads();

    for (int base = 0; base < N; base += 8192) {
        const int idx0 = base + tid * 8;
        int vals[8], tsum = 0;
#pragma unroll
        for (int t = 0; t < 8; t++) {
            vals[t] = (idx0 + t < N) ? g_deg[idx0 + t] : 0;
            tsum += vals[t];
        }
        const int carry_old = s_carry;
        ssum[tid] = tsum;
        __syncthreads();
        for (int off = 1; off < 1024; off <<= 1) {
            int v = (tid >= off) ? ssum[tid - off] : 0;
            __syncthreads();
            ssum[tid] += v;
            __syncthreads();
        }
        int run = carry_old + ssum[tid] - tsum;  // exclusive prefix of first elem
#pragma unroll
        for (int t = 0; t < 8; t++) {
            if (idx0 + t < N) { g_rowptr[idx0 + t] = run; g_cursor[idx0 + t] = run; }
            run += vals[t];
        }
        __syncthreads();
        if (tid == 0) s_carry = carry_old + ssum[1023];
        __syncthreads();
    }
    if (tid == 0) g_rowptr[N] = E;
}

__global__ __launch_bounds__(256) void scatter_kernel(const int* __restrict__ ei, int E)
{
    const int i = blockIdx.x * blockDim.x + threadIdx.x;   // 2 edges per thread
    const int e0 = i * 2;
    if (e0 >= E) return;
    const int4 p = ((const int4*)ei)[i];
    g_src[atomicAdd(&g_cursor[p.y], 1)] = p.x;
    if (e0 + 1 < E) g_src[atomicAdd(&g_cursor[p.w], 1)] = p.z;
}

// ============================================================================
// Fused single-pass per-node attention: one warp per destination node.
// Lane l holds dims [4l, 4l+4); head of lane = l >> 2.
// Identity: attn = exp(s - mx)/(sum exp(si - mx) + exp(-mx))
//               == exp(s)    /(sum exp(si)      + 1)          (mx cancels)
// So a single pass suffices: acc = sum exp(si)*v[ri], dsum = sum exp(si),
// out = acc / (dsum + 1) / max(deg, 1).
// src indices fetched coalesced 32-wide, broadcast via shfl.
// ============================================================================
__global__ __launch_bounds__(256) void node_attn_kernel(int N)
{
    const int nid  = blockIdx.x * 8 + (threadIdx.x >> 5);
    const int lane = threadIdx.x & 31;
    if (nid >= N) return;

    const int start = g_rowptr[nid];
    const int end   = g_rowptr[nid + 1];
    const int deg   = end - start;

    const float4 qv = ((const float4*)g_q)[nid * 32 + lane];

    float4 acc = make_float4(0.f, 0.f, 0.f, 0.f);
    float dsum = 0.0f;

    for (int base = start; base < end; base += 32) {
        const int n_batch = min(32, end - base);
        int my_src = 0;
        if (base + lane < end) my_src = g_src[base + lane];

#pragma unroll 4
        for (int t = 0; t < n_batch; t++) {
            const int r = __shfl_sync(0xffffffffu, my_src, t);
            const float4 kv = ((const float4*)g_k)[r * 32 + lane];
            const float4 vv = ((const float4*)g_v)[r * 32 + lane];
            float s = qv.x * kv.x + qv.y * kv.y + qv.z * kv.z + qv.w * kv.w;
            s += __shfl_xor_sync(0xffffffffu, s, 1);
            s += __shfl_xor_sync(0xffffffffu, s, 2);   // full head dot on all 4 lanes
            const float ex = __expf(s * 0.25f);        // / sqrt(HD=16)
            acc.x = fmaf(ex, vv.x, acc.x);
            acc.y = fmaf(ex, vv.y, acc.y);
            acc.z = fmaf(ex, vv.z, acc.z);
            acc.w = fmaf(ex, vv.w, acc.w);
            dsum += ex;
        }
    }

    const float scale = 1.0f / ((dsum + 1.0f) * (float)max(deg, 1));
    acc.x *= scale; acc.y *= scale; acc.z *= scale; acc.w *= scale;
    ((float4*)g_agg)[nid * 32 + lane] = acc;
}

// ============================================================================
// Launch
// ============================================================================
extern "C" void kernel_launch(void* const* d_in, const int* in_sizes, int n_in,
                              void* d_out, int out_size)
{
    const float* feats = (const float*)d_in[0];
    const int*   ei    = (const int*)d_in[1];
    const float* Wq = (const float*)d_in[2]; const float* bq = (const float*)d_in[3];
    const float* Wk = (const float*)d_in[4]; const float* bk = (const float*)d_in[5];
    const float* Wv = (const float*)d_in[6]; const float* bv = (const float*)d_in[7];
    const float* Wo = (const float*)d_in[8]; const float* bo = (const float*)d_in[9];
    float* out = (float*)d_out;

    const int N = in_sizes[0] / D;
    const int E = in_sizes[1] / 2;

    float *q, *k, *v, *agg;
    int *deg;
    cudaGetSymbolAddress((void**)&q,   g_q);
    cudaGetSymbolAddress((void**)&k,   g_k);
    cudaGetSymbolAddress((void**)&v,   g_v);
    cudaGetSymbolAddress((void**)&agg, g_agg);
    cudaGetSymbolAddress((void**)&deg, g_deg);

    cudaMemsetAsync(deg, 0, (size_t)N * sizeof(int));

    const int gblocks = (N + 127) / 128;
    gemm_bias_kernel<<<gblocks, 256>>>(feats, Wq, bq, q, N);
    gemm_bias_kernel<<<gblocks, 256>>>(feats, Wk, bk, k, N);
    gemm_bias_kernel<<<gblocks, 256>>>(feats, Wv, bv, v, N);

    deg_kernel<<<(E / 2 + 255) / 256, 256>>>(ei, E);
    scan_kernel<<<1, 1024>>>(N, E);
    scatter_kernel<<<(E / 2 + 255) / 256, 256>>>(ei, E);

    node_attn_kernel<<<(N + 7) / 8, 256>>>(N);

    gemm_bias_kernel<<<gblocks, 256>>>(agg, Wo, bo, out, N);
}

// round 9
// speedup vs baseline: 1.5032x; 1.0553x over previous
#include <cuda_runtime.h>

#define D 128
#define H 8
#define MAXN 50000
#define MAXE 800000

// ---- scratch (static device globals; no allocation allowed) ----
__device__ float g_q[MAXN * D];
__device__ float g_k[MAXN * D];
__device__ float g_v[MAXN * D];
__device__ float g_agg[MAXN * D];
__device__ int   g_deg[MAXN];
__device__ int   g_rowptr[MAXN + 1];
__device__ int   g_cursor[MAXN];
__device__ int   g_src[MAXE];                  // source node r per CSR slot

// ============================================================================
// Packed-f32x2 helpers (FFMA2: 2 FMAs per issue slot on sm_103a)
// ============================================================================
__device__ __forceinline__ void fma2(unsigned long long& d,
                                     unsigned long long a,
                                     unsigned long long b) {
    asm("fma.rn.f32x2 %0, %1, %2, %0;" : "+l"(d) : "l"(a), "l"(b));
}
__device__ __forceinline__ unsigned long long pack2(float x) {
    unsigned long long r;
    asm("mov.b64 %0, {%1, %1};" : "=l"(r) : "f"(x));
    return r;
}
__device__ __forceinline__ void unpack2(unsigned long long d, float& lo, float& hi) {
    asm("mov.b64 {%0, %1}, %2;" : "=f"(lo), "=f"(hi) : "l"(d));
}

// ============================================================================
// GEMM tile body: C[bm..bm+128, :] = A[rows] @ W^T + bias
// BM=128, BN=128, BK=16, 256 threads, FFMA2 inner product.
// ============================================================================
__device__ __forceinline__ void gemm_tile(
    const float* __restrict__ A, const float* __restrict__ W,
    const float* __restrict__ bias, float* __restrict__ C, int M, int bm)
{
    __shared__ __align__(16) float sA[16][132];
    __shared__ __align__(16) float sW[16][132];

    const int tid = threadIdx.x;
    const int tx  = tid & 15;      // col-pair group: cols 2*tx + 32*jp (+0/+1)
    const int ty  = tid >> 4;      // row group: rows ty + 16*i
    const int lr  = tid >> 1;      // load row 0..127
    const int lc  = (tid & 1) * 8; // load col offset within 16-wide K slab

    unsigned long long acc[8][4];
#pragma unroll
    for (int i = 0; i < 8; i++)
#pragma unroll
        for (int j = 0; j < 4; j++) acc[i][j] = 0ull;

    for (int k0 = 0; k0 < D; k0 += 16) {
        const int grow = bm + lr;
        float4 a0 = make_float4(0.f, 0.f, 0.f, 0.f), a1 = a0;
        if (grow < M) {
            a0 = *(const float4*)(A + (size_t)grow * D + k0 + lc);
            a1 = *(const float4*)(A + (size_t)grow * D + k0 + lc + 4);
        }
        sA[lc + 0][lr] = a0.x; sA[lc + 1][lr] = a0.y;
        sA[lc + 2][lr] = a0.z; sA[lc + 3][lr] = a0.w;
        sA[lc + 4][lr] = a1.x; sA[lc + 5][lr] = a1.y;
        sA[lc + 6][lr] = a1.z; sA[lc + 7][lr] = a1.w;

        const float4 w0 = *(const float4*)(W + (size_t)lr * D + k0 + lc);
        const float4 w1 = *(const float4*)(W + (size_t)lr * D + k0 + lc + 4);
        sW[lc + 0][lr] = w0.x; sW[lc + 1][lr] = w0.y;
        sW[lc + 2][lr] = w0.z; sW[lc + 3][lr] = w0.w;
        sW[lc + 4][lr] = w1.x; sW[lc + 5][lr] = w1.y;
        sW[lc + 6][lr] = w1.z; sW[lc + 7][lr] = w1.w;
        __syncthreads();

#pragma unroll
        for (int kk = 0; kk < 16; kk++) {
            unsigned long long ad[8], wd[4];
#pragma unroll
            for (int i = 0; i < 8; i++) ad[i] = pack2(sA[kk][ty + i * 16]);
#pragma unroll
            for (int jp = 0; jp < 4; jp++)
                wd[jp] = *(const unsigned long long*)&sW[kk][2 * tx + 32 * jp];
#pragma unroll
            for (int i = 0; i < 8; i++)
#pragma unroll
                for (int jp = 0; jp < 4; jp++)
                    fma2(acc[i][jp], ad[i], wd[jp]);
        }
        __syncthreads();
    }

    float2 bv[4];
#pragma unroll
    for (int jp = 0; jp < 4; jp++)
        bv[jp] = *(const float2*)&bias[2 * tx + 32 * jp];

#pragma unroll
    for (int i = 0; i < 8; i++) {
        const int row = bm + ty + i * 16;
        if (row >= M) continue;
#pragma unroll
        for (int jp = 0; jp < 4; jp++) {
            float lo, hi;
            unpack2(acc[i][jp], lo, hi);
            *(float2*)&C[(size_t)row * D + 2 * tx + 32 * jp] =
                make_float2(lo + bv[jp].x, hi + bv[jp].y);
        }
    }
}

// ============================================================================
// CSR stage bodies
// ============================================================================
__device__ __forceinline__ void deg_body(const int* __restrict__ ei, int E, int b)
{
    const int base = (b * 256 + threadIdx.x) * 8;   // 8 edges per thread
    if (base >= E) return;
#pragma unroll
    for (int t = 0; t < 4; t++) {
        const int e = base + t * 2;
        if (e < E) {
            const int4 p = ((const int4*)ei)[e >> 1];   // {r0,c0,r1,c1}
            atomicAdd(&g_deg[p.y], 1);
            if (e + 1 < E) atomicAdd(&g_deg[p.w], 1);
        }
    }
}

__device__ __forceinline__ void scatter_body(const int* __restrict__ ei, int E, int b)
{
    const int base = (b * 256 + threadIdx.x) * 8;
    if (base >= E) return;
#pragma unroll
    for (int t = 0; t < 4; t++) {
        const int e = base + t * 2;
        if (e < E) {
            const int4 p = ((const int4*)ei)[e >> 1];
            g_src[atomicAdd(&g_cursor[p.y], 1)] = p.x;
            if (e + 1 < E) g_src[atomicAdd(&g_cursor[p.w], 1)] = p.z;
        }
    }
}

// 256-thread exclusive scan: rowptr + cursor seed. chunk-per-thread + shfl scan.
__device__ __forceinline__ void scan_body(int N, int E)
{
    __shared__ int warp_sums[8];
    const int tid   = threadIdx.x;
    const int chunk = (N + 255) / 256;
    const int lo    = tid * chunk;
    const int hi    = min(lo + chunk, N);

    int sum = 0;
    for (int i = lo; i < hi; i++) sum += g_deg[i];

    const int lane = tid & 31, wid = tid >> 5;
    int val = sum;
#pragma unroll
    for (int off = 1; off < 32; off <<= 1) {
        const int n = __shfl_up_sync(0xffffffffu, val, off);
        if (lane >= off) val += n;
    }
    if (lane == 31) warp_sums[wid] = val;
    __syncthreads();
    if (wid == 0 && lane < 8) {
        int w = warp_sums[lane];
#pragma unroll
        for (int off = 1; off < 8; off <<= 1) {
            const int n = __shfl_up_sync(0xffu, w, off);
            if (lane >= off) w += n;
        }
        warp_sums[lane] = w;
    }
    __syncthreads();

    int run = val - sum + (wid > 0 ? warp_sums[wid - 1] : 0);  // exclusive prefix
    for (int i = lo; i < hi; i++) {
        const int d = g_deg[i];
        g_rowptr[i] = run; g_cursor[i] = run;
        run += d;
    }
    if (tid == 0) g_rowptr[N] = E;
}

// ============================================================================
// Fat kernels: GEMM blocks [0, gblocks), CSR-stage blocks [gblocks, ...)
// ============================================================================
__global__ __launch_bounds__(256) void k_gemm_deg(
    const float* __restrict__ A, const float* __restrict__ W,
    const float* __restrict__ bias, float* __restrict__ C, int M, int gblocks,
    const int* __restrict__ ei, int E)
{
    if ((int)blockIdx.x < gblocks) gemm_tile(A, W, bias, C, M, blockIdx.x * 128);
    else                           deg_body(ei, E, blockIdx.x - gblocks);
}

__global__ __launch_bounds__(256) void k_gemm_scan(
    const float* __restrict__ A, const float* __restrict__ W,
    const float* __restrict__ bias, float* __restrict__ C, int M, int gblocks,
    int N, int E)
{
    if ((int)blockIdx.x < gblocks)           gemm_tile(A, W, bias, C, M, blockIdx.x * 128);
    else if ((int)blockIdx.x == gblocks)     scan_body(N, E);
}

__global__ __launch_bounds__(256) void k_gemm_scatter(
    const float* __restrict__ A, const float* __restrict__ W,
    const float* __restrict__ bias, float* __restrict__ C, int M, int gblocks,
    const int* __restrict__ ei, int E)
{
    if ((int)blockIdx.x < gblocks) gemm_tile(A, W, bias, C, M, blockIdx.x * 128);
    else                           scatter_body(ei, E, blockIdx.x - gblocks);
}

__global__ __launch_bounds__(256) void gemm_bias_kernel(
    const float* __restrict__ A, const float* __restrict__ W,
    const float* __restrict__ bias, float* __restrict__ C, int M)
{
    gemm_tile(A, W, bias, C, M, blockIdx.x * 128);
}

// ============================================================================
// Fused single-pass per-node attention: one warp per destination node.
// attn = exp(s)/(sum exp(si) + 1)  (max-shift cancels identically).
// 2-edge software pipeline, dual accumulators, __ldg gathers.
// ============================================================================
__global__ __launch_bounds__(256) void node_attn_kernel(int N)
{
    const int nid  = blockIdx.x * 8 + (threadIdx.x >> 5);
    const int lane = threadIdx.x & 31;
    if (nid >= N) return;

    const int start = g_rowptr[nid];
    const int end   = g_rowptr[nid + 1];
    const int deg   = end - start;

    const float4 qv = __ldg(((const float4*)g_q) + nid * 32 + lane);

    float4 acc0 = make_float4(0.f, 0.f, 0.f, 0.f);
    float4 acc1 = make_float4(0.f, 0.f, 0.f, 0.f);
    float d0 = 0.0f, d1 = 0.0f;

    for (int base = start; base < end; base += 32) {
        const int nb = min(32, end - base);
        int my_src = 0;
        if (base + lane < end) my_src = g_src[base + lane];

        int t = 0;
#pragma unroll 2
        for (; t + 2 <= nb; t += 2) {
            const int r0 = __shfl_sync(0xffffffffu, my_src, t);
            const int r1 = __shfl_sync(0xffffffffu, my_src, t + 1);
            const float4 k0 = __ldg(((const float4*)g_k) + r0 * 32 + lane);
            const float4 v0 = __ldg(((const float4*)g_v) + r0 * 32 + lane);
            const float4 k1 = __ldg(((const float4*)g_k) + r1 * 32 + lane);
            const float4 v1 = __ldg(((const float4*)g_v) + r1 * 32 + lane);

            float s0 = k0.x * qv.x + k0.y * qv.y + k0.z * qv.z + k0.w * qv.w;
            float s1 = k1.x * qv.x + k1.y * qv.y + k1.z * qv.z + k1.w * qv.w;
            s0 += __shfl_xor_sync(0xffffffffu, s0, 1);
            s1 += __shfl_xor_sync(0xffffffffu, s1, 1);
            s0 += __shfl_xor_sync(0xffffffffu, s0, 2);
            s1 += __shfl_xor_sync(0xffffffffu, s1, 2);

            const float e0 = __expf(s0 * 0.25f);
            const float e1 = __expf(s1 * 0.25f);
            acc0.x = fmaf(e0, v0.x, acc0.x); acc1.x = fmaf(e1, v1.x, acc1.x);
            acc0.y = fmaf(e0, v0.y, acc0.y); acc1.y = fmaf(e1, v1.y, acc1.y);
            acc0.z = fmaf(e0, v0.z, acc0.z); acc1.z = fmaf(e1, v1.z, acc1.z);
            acc0.w = fmaf(e0, v0.w, acc0.w); acc1.w = fmaf(e1, v1.w, acc1.w);
            d0 += e0; d1 += e1;
        }
        if (t < nb) {
            const int r0 = __shfl_sync(0xffffffffu, my_src, t);
            const float4 k0 = __ldg(((const float4*)g_k) + r0 * 32 + lane);
            const float4 v0 = __ldg(((const float4*)g_v) + r0 * 32 + lane);
            float s0 = k0.x * qv.x + k0.y * qv.y + k0.z * qv.z + k0.w * qv.w;
            s0 += __shfl_xor_sync(0xffffffffu, s0, 1);
            s0 += __shfl_xor_sync(0xffffffffu, s0, 2);
            const float e0 = __expf(s0 * 0.25f);
            acc0.x = fmaf(e0, v0.x, acc0.x);
            acc0.y = fmaf(e0, v0.y, acc0.y);
            acc0.z = fmaf(e0, v0.z, acc0.z);
            acc0.w = fmaf(e0, v0.w, acc0.w);
            d0 += e0;
        }
    }

    const float scale = 1.0f / ((d0 + d1 + 1.0f) * (float)max(deg, 1));
    float4 outv;
    outv.x = (acc0.x + acc1.x) * scale;
    outv.y = (acc0.y + acc1.y) * scale;
    outv.z = (acc0.z + acc1.z) * scale;
    outv.w = (acc0.w + acc1.w) * scale;
    ((float4*)g_agg)[nid * 32 + lane] = outv;
}

// ============================================================================
// Launch
// ============================================================================
extern "C" void kernel_launch(void* const* d_in, const int* in_sizes, int n_in,
                              void* d_out, int out_size)
{
    const float* feats = (const float*)d_in[0];
    const int*   ei    = (const int*)d_in[1];
    const float* Wq = (const float*)d_in[2]; const float* bq = (const float*)d_in[3];
    const float* Wk = (const float*)d_in[4]; const float* bk = (const float*)d_in[5];
    const float* Wv = (const float*)d_in[6]; const float* bv = (const float*)d_in[7];
    const float* Wo = (const float*)d_in[8]; const float* bo = (const float*)d_in[9];
    float* out = (float*)d_out;

    const int N = in_sizes[0] / D;
    const int E = in_sizes[1] / 2;

    float *q, *k, *v, *agg;
    int *deg;
    cudaGetSymbolAddress((void**)&q,   g_q);
    cudaGetSymbolAddress((void**)&k,   g_k);
    cudaGetSymbolAddress((void**)&v,   g_v);
    cudaGetSymbolAddress((void**)&agg, g_agg);
    cudaGetSymbolAddress((void**)&deg, g_deg);

    cudaMemsetAsync(deg, 0, (size_t)N * sizeof(int));

    const int gblocks = (N + 127) / 128;
    const int eb8     = (E + 2047) / 2048;   // 8 edges/thread, 256 threads

    k_gemm_deg    <<<gblocks + eb8, 256>>>(feats, Wq, bq, q, N, gblocks, ei, E);
    k_gemm_scan   <<<gblocks + 1,   256>>>(feats, Wk, bk, k, N, gblocks, N, E);
    k_gemm_scatter<<<gblocks + eb8, 256>>>(feats, Wv, bv, v, N, gblocks, ei, E);

    node_attn_kernel<<<(N + 7) / 8, 256>>>(N);

    gemm_bias_kernel<<<gblocks, 256>>>(agg, Wo, bo, out, N);
}

// round 13
// speedup vs baseline: 1.5446x; 1.0276x over previous
#include <cuda_runtime.h>

#define D 128
#define H 8
#define MAXN 50000
#define MAXE 800000

// ---- scratch (static device globals; no allocation allowed) ----
__device__ float g_q[MAXN * D];
__device__ float g_k[MAXN * D];
__device__ float g_v[MAXN * D];
__device__ float g_agg[MAXN * D];
__device__ int   g_deg[MAXN];
__device__ int   g_rowptr[MAXN + 1];
__device__ int   g_cursor[MAXN];
__device__ int   g_src[MAXE];                  // source node r per CSR slot

// ============================================================================
// Packed-f32x2 helpers (FFMA2: 2 FMAs per issue slot on sm_103a)
// ============================================================================
__device__ __forceinline__ void fma2(unsigned long long& d,
                                     unsigned long long a,
                                     unsigned long long b) {
    asm("fma.rn.f32x2 %0, %1, %2, %0;" : "+l"(d) : "l"(a), "l"(b));
}
__device__ __forceinline__ unsigned long long pack2(float x) {
    unsigned long long r;
    asm("mov.b64 %0, {%1, %1};" : "=l"(r) : "f"(x));
    return r;
}
__device__ __forceinline__ void unpack2(unsigned long long d, float& lo, float& hi) {
    asm("mov.b64 {%0, %1}, %2;" : "=f"(lo), "=f"(hi) : "l"(d));
}

// ============================================================================
// GEMM tile body: C[bm..bm+128, :] = A[rows] @ W^T + bias
// BM=128, BN=128, BK=16, 256 threads, FFMA2 inner product.
// Double-buffered smem, register prefetch, ONE __syncthreads per K-slab.
// ============================================================================
__device__ __forceinline__ void gemm_tile(
    const float* __restrict__ A, const float* __restrict__ W,
    const float* __restrict__ bias, float* __restrict__ C, int M, int bm)
{
    __shared__ __align__(16) float sA[2][16][132];
    __shared__ __align__(16) float sW[2][16][132];

    const int tid = threadIdx.x;
    const int tx  = tid & 15;      // col-pair group: cols 2*tx + 32*jp (+0/+1)
    const int ty  = tid >> 4;      // row group: rows ty + 16*i
    const int lr  = tid >> 1;      // load row 0..127
    const int lc  = (tid & 1) * 8; // load col offset within 16-wide K slab

    const int   grow  = bm + lr;
    const bool  rowok = (grow < M);
    const float* Arow = A + (size_t)grow * D + lc;
    const float* Wrow = W + (size_t)lr * D + lc;

    unsigned long long acc[8][4];
#pragma unroll
    for (int i = 0; i < 8; i++)
#pragma unroll
        for (int j = 0; j < 4; j++) acc[i][j] = 0ull;

    // prologue: load slab 0 into buffer 0
    {
        float4 a0 = make_float4(0.f,0.f,0.f,0.f), a1 = a0;
        if (rowok) { a0 = *(const float4*)(Arow); a1 = *(const float4*)(Arow + 4); }
        const float4 w0 = *(const float4*)(Wrow);
        const float4 w1 = *(const float4*)(Wrow + 4);
        sA[0][lc+0][lr]=a0.x; sA[0][lc+1][lr]=a0.y; sA[0][lc+2][lr]=a0.z; sA[0][lc+3][lr]=a0.w;
        sA[0][lc+4][lr]=a1.x; sA[0][lc+5][lr]=a1.y; sA[0][lc+6][lr]=a1.z; sA[0][lc+7][lr]=a1.w;
        sW[0][lc+0][lr]=w0.x; sW[0][lc+1][lr]=w0.y; sW[0][lc+2][lr]=w0.z; sW[0][lc+3][lr]=w0.w;
        sW[0][lc+4][lr]=w1.x; sW[0][lc+5][lr]=w1.y; sW[0][lc+6][lr]=w1.z; sW[0][lc+7][lr]=w1.w;
    }
    __syncthreads();

    int cur = 0;
#pragma unroll
    for (int k0 = 16; k0 < D; k0 += 16) {
        // prefetch next slab (LDGs issued before the FFMA block)
        float4 a0 = make_float4(0.f,0.f,0.f,0.f), a1 = a0;
        if (rowok) { a0 = *(const float4*)(Arow + k0); a1 = *(const float4*)(Arow + k0 + 4); }
        const float4 w0 = *(const float4*)(Wrow + k0);
        const float4 w1 = *(const float4*)(Wrow + k0 + 4);

        // compute current slab
#pragma unroll
        for (int kk = 0; kk < 16; kk++) {
            unsigned long long ad[8], wd[4];
#pragma unroll
            for (int i = 0; i < 8; i++) ad[i] = pack2(sA[cur][kk][ty + i * 16]);
#pragma unroll
            for (int jp = 0; jp < 4; jp++)
                wd[jp] = *(const unsigned long long*)&sW[cur][kk][2 * tx + 32 * jp];
#pragma unroll
            for (int i = 0; i < 8; i++)
#pragma unroll
                for (int jp = 0; jp < 4; jp++)
                    fma2(acc[i][jp], ad[i], wd[jp]);
        }

        // store prefetched slab into the other buffer
        const int nxt = cur ^ 1;
        sA[nxt][lc+0][lr]=a0.x; sA[nxt][lc+1][lr]=a0.y; sA[nxt][lc+2][lr]=a0.z; sA[nxt][lc+3][lr]=a0.w;
        sA[nxt][lc+4][lr]=a1.x; sA[nxt][lc+5][lr]=a1.y; sA[nxt][lc+6][lr]=a1.z; sA[nxt][lc+7][lr]=a1.w;
        sW[nxt][lc+0][lr]=w0.x; sW[nxt][lc+1][lr]=w0.y; sW[nxt][lc+2][lr]=w0.z; sW[nxt][lc+3][lr]=w0.w;
        sW[nxt][lc+4][lr]=w1.x; sW[nxt][lc+5][lr]=w1.y; sW[nxt][lc+6][lr]=w1.z; sW[nxt][lc+7][lr]=w1.w;

        __syncthreads();   // publishes nxt AND protects cur from next overwrite
        cur = nxt;
    }

    // epilogue slab
#pragma unroll
    for (int kk = 0; kk < 16; kk++) {
        unsigned long long ad[8], wd[4];
#pragma unroll
        for (int i = 0; i < 8; i++) ad[i] = pack2(sA[cur][kk][ty + i * 16]);
#pragma unroll
        for (int jp = 0; jp < 4; jp++)
            wd[jp] = *(const unsigned long long*)&sW[cur][kk][2 * tx + 32 * jp];
#pragma unroll
        for (int i = 0; i < 8; i++)
#pragma unroll
            for (int jp = 0; jp < 4; jp++)
                fma2(acc[i][jp], ad[i], wd[jp]);
    }

    float2 bv[4];
#pragma unroll
    for (int jp = 0; jp < 4; jp++)
        bv[jp] = *(const float2*)&bias[2 * tx + 32 * jp];

#pragma unroll
    for (int i = 0; i < 8; i++) {
        const int row = bm + ty + i * 16;
        if (row >= M) continue;
#pragma unroll
        for (int jp = 0; jp < 4; jp++) {
            float lo, hi;
            unpack2(acc[i][jp], lo, hi);
            *(float2*)&C[(size_t)row * D + 2 * tx + 32 * jp] =
                make_float2(lo + bv[jp].x, hi + bv[jp].y);
        }
    }
}

// ============================================================================
// CSR stage bodies
// ============================================================================
__device__ __forceinline__ void deg_body(const int* __restrict__ ei, int E, int b)
{
    const int base = (b * 256 + threadIdx.x) * 8;   // 8 edges per thread
    if (base >= E) return;
#pragma unroll
    for (int t = 0; t < 4; t++) {
        const int e = base + t * 2;
        if (e < E) {
            const int4 p = ((const int4*)ei)[e >> 1];   // {r0,c0,r1,c1}
            atomicAdd(&g_deg[p.y], 1);
            if (e + 1 < E) atomicAdd(&g_deg[p.w], 1);
        }
    }
}

__device__ __forceinline__ void scatter_body(const int* __restrict__ ei, int E, int b)
{
    const int base = (b * 256 + threadIdx.x) * 8;
    if (base >= E) return;
#pragma unroll
    for (int t = 0; t < 4; t++) {
        const int e = base + t * 2;
        if (e < E) {
            const int4 p = ((const int4*)ei)[e >> 1];
            g_src[atomicAdd(&g_cursor[p.y], 1)] = p.x;
            if (e + 1 < E) g_src[atomicAdd(&g_cursor[p.w], 1)] = p.z;
        }
    }
}

// 256-thread exclusive scan: rowptr + cursor seed. chunk-per-thread + shfl scan.
__device__ __forceinline__ void scan_body(int N, int E)
{
    __shared__ int warp_sums[8];
    const int tid   = threadIdx.x;
    const int chunk = (N + 255) / 256;
    const int lo    = tid * chunk;
    const int hi    = min(lo + chunk, N);

    int sum = 0;
    for (int i = lo; i < hi; i++) sum += g_deg[i];

    const int lane = tid & 31, wid = tid >> 5;
    int val = sum;
#pragma unroll
    for (int off = 1; off < 32; off <<= 1) {
        const int n = __shfl_up_sync(0xffffffffu, val, off);
        if (lane >= off) val += n;
    }
    if (lane == 31) warp_sums[wid] = val;
    __syncthreads();
    if (wid == 0 && lane < 8) {
        int w = warp_sums[lane];
#pragma unroll
        for (int off = 1; off < 8; off <<= 1) {
            const int n = __shfl_up_sync(0xffu, w, off);
            if (lane >= off) w += n;
        }
        warp_sums[lane] = w;
    }
    __syncthreads();

    int run = val - sum + (wid > 0 ? warp_sums[wid - 1] : 0);  // exclusive prefix
    for (int i = lo; i < hi; i++) {
        const int d = g_deg[i];
        g_rowptr[i] = run; g_cursor[i] = run;
        run += d;
    }
    if (tid == 0) g_rowptr[N] = E;
}

// ============================================================================
// Fat kernels: GEMM blocks [0, gblocks), CSR-stage blocks [gblocks, ...)
// ============================================================================
__global__ __launch_bounds__(256) void k_gemm_deg(
    const float* __restrict__ A, const float* __restrict__ W,
    const float* __restrict__ bias, float* __restrict__ C, int M, int gblocks,
    const int* __restrict__ ei, int E)
{
    if ((int)blockIdx.x < gblocks) gemm_tile(A, W, bias, C, M, blockIdx.x * 128);
    else                           deg_body(ei, E, blockIdx.x - gblocks);
}

__global__ __launch_bounds__(256) void k_gemm_scan(
    const float* __restrict__ A, const float* __restrict__ W,
    const float* __restrict__ bias, float* __restrict__ C, int M, int gblocks,
    int N, int E)
{
    if ((int)blockIdx.x < gblocks)           gemm_tile(A, W, bias, C, M, blockIdx.x * 128);
    else if ((int)blockIdx.x == gblocks)     scan_body(N, E);
}

__global__ __launch_bounds__(256) void k_gemm_scatter(
    const float* __restrict__ A, const float* __restrict__ W,
    const float* __restrict__ bias, float* __restrict__ C, int M, int gblocks,
    const int* __restrict__ ei, int E)
{
    if ((int)blockIdx.x < gblocks) gemm_tile(A, W, bias, C, M, blockIdx.x * 128);
    else                           scatter_body(ei, E, blockIdx.x - gblocks);
}

__global__ __launch_bounds__(256) void gemm_bias_kernel(
    const float* __restrict__ A, const float* __restrict__ W,
    const float* __restrict__ bias, float* __restrict__ C, int M)
{
    gemm_tile(A, W, bias, C, M, blockIdx.x * 128);
}

// ============================================================================
// Fused single-pass per-node attention: one warp per destination node.
// attn = exp(s)/(sum exp(si) + 1)  (max-shift cancels identically).
// 4-edge software pipeline (8 gathers in flight), quad accumulators.
// ============================================================================
__global__ __launch_bounds__(256) void node_attn_kernel(int N)
{
    const int nid  = blockIdx.x * 8 + (threadIdx.x >> 5);
    const int lane = threadIdx.x & 31;
    if (nid >= N) return;

    const int start = g_rowptr[nid];
    const int end   = g_rowptr[nid + 1];
    const int deg   = end - start;

    const float4 qv = __ldg(((const float4*)g_q) + nid * 32 + lane);

    float4 acc0 = make_float4(0.f,0.f,0.f,0.f), acc1 = acc0, acc2 = acc0, acc3 = acc0;
    float d0 = 0.f, d1 = 0.f, d2 = 0.f, d3 = 0.f;

    for (int base = start; base < end; base += 32) {
        const int nb = min(32, end - base);
        int my_src = 0;
        if (base + lane < end) my_src = g_src[base + lane];

        int t = 0;
        for (; t + 4 <= nb; t += 4) {
            const int r0 = __shfl_sync(0xffffffffu, my_src, t);
            const int r1 = __shfl_sync(0xffffffffu, my_src, t + 1);
            const int r2 = __shfl_sync(0xffffffffu, my_src, t + 2);
            const int r3 = __shfl_sync(0xffffffffu, my_src, t + 3);
            const float4 k0 = __ldg(((const float4*)g_k) + r0 * 32 + lane);
            const float4 v0 = __ldg(((const float4*)g_v) + r0 * 32 + lane);
            const float4 k1 = __ldg(((const float4*)g_k) + r1 * 32 + lane);
            const float4 v1 = __ldg(((const float4*)g_v) + r1 * 32 + lane);
            const float4 k2 = __ldg(((const float4*)g_k) + r2 * 32 + lane);
            const float4 v2 = __ldg(((const float4*)g_v) + r2 * 32 + lane);
            const float4 k3 = __ldg(((const float4*)g_k) + r3 * 32 + lane);
            const float4 v3 = __ldg(((const float4*)g_v) + r3 * 32 + lane);

            float s0 = k0.x*qv.x + k0.y*qv.y + k0.z*qv.z + k0.w*qv.w;
            float s1 = k1.x*qv.x + k1.y*qv.y + k1.z*qv.z + k1.w*qv.w;
            float s2 = k2.x*qv.x + k2.y*qv.y + k2.z*qv.z + k2.w*qv.w;
            float s3 = k3.x*qv.x + k3.y*qv.y + k3.z*qv.z + k3.w*qv.w;
            s0 += __shfl_xor_sync(0xffffffffu, s0, 1);
            s1 += __shfl_xor_sync(0xffffffffu, s1, 1);
            s2 += __shfl_xor_sync(0xffffffffu, s2, 1);
            s3 += __shfl_xor_sync(0xffffffffu, s3, 1);
            s0 += __shfl_xor_sync(0xffffffffu, s0, 2);
            s1 += __shfl_xor_sync(0xffffffffu, s1, 2);
            s2 += __shfl_xor_sync(0xffffffffu, s2, 2);
            s3 += __shfl_xor_sync(0xffffffffu, s3, 2);

            const float e0 = __expf(s0 * 0.25f);
            const float e1 = __expf(s1 * 0.25f);
            const float e2 = __expf(s2 * 0.25f);
            const float e3 = __expf(s3 * 0.25f);
            acc0.x = fmaf(e0, v0.x, acc0.x); acc1.x = fmaf(e1, v1.x, acc1.x);
            acc2.x = fmaf(e2, v2.x, acc2.x); acc3.x = fmaf(e3, v3.x, acc3.x);
            acc0.y = fmaf(e0, v0.y, acc0.y); acc1.y = fmaf(e1, v1.y, acc1.y);
            acc2.y = fmaf(e2, v2.y, acc2.y); acc3.y = fmaf(e3, v3.y, acc3.y);
            acc0.z = fmaf(e0, v0.z, acc0.z); acc1.z = fmaf(e1, v1.z, acc1.z);
            acc2.z = fmaf(e2, v2.z, acc2.z); acc3.z = fmaf(e3, v3.z, acc3.z);
            acc0.w = fmaf(e0, v0.w, acc0.w); acc1.w = fmaf(e1, v1.w, acc1.w);
            acc2.w = fmaf(e2, v2.w, acc2.w); acc3.w = fmaf(e3, v3.w, acc3.w);
            d0 += e0; d1 += e1; d2 += e2; d3 += e3;
        }
        for (; t < nb; t++) {
            const int r0 = __shfl_sync(0xffffffffu, my_src, t);
            const float4 k0 = __ldg(((const float4*)g_k) + r0 * 32 + lane);
            const float4 v0 = __ldg(((const float4*)g_v) + r0 * 32 + lane);
            float s0 = k0.x*qv.x + k0.y*qv.y + k0.z*qv.z + k0.w*qv.w;
            s0 += __shfl_xor_sync(0xffffffffu, s0, 1);
            s0 += __shfl_xor_sync(0xffffffffu, s0, 2);
            const float e0 = __expf(s0 * 0.25f);
            acc0.x = fmaf(e0, v0.x, acc0.x);
            acc0.y = fmaf(e0, v0.y, acc0.y);
            acc0.z = fmaf(e0, v0.z, acc0.z);
            acc0.w = fmaf(e0, v0.w, acc0.w);
            d0 += e0;
        }
    }

    const float scale = 1.0f / ((d0 + d1 + d2 + d3 + 1.0f) * (float)max(deg, 1));
    float4 outv;
    outv.x = (acc0.x + acc1.x + acc2.x + acc3.x) * scale;
    outv.y = (acc0.y + acc1.y + acc2.y + acc3.y) * scale;
    outv.z = (acc0.z + acc1.z + acc2.z + acc3.z) * scale;
    outv.w = (acc0.w + acc1.w + acc2.w + acc3.w) * scale;
    ((float4*)g_agg)[nid * 32 + lane] = outv;
}

// ============================================================================
// Launch
// ============================================================================
extern "C" void kernel_launch(void* const* d_in, const int* in_sizes, int n_in,
                              void* d_out, int out_size)
{
    const float* feats = (const float*)d_in[0];
    const int*   ei    = (const int*)d_in[1];
    const float* Wq = (const float*)d_in[2]; const float* bq = (const float*)d_in[3];
    const float* Wk = (const float*)d_in[4]; const float* bk = (const float*)d_in[5];
    const float* Wv = (const float*)d_in[6]; const float* bv = (const float*)d_in[7];
    const float* Wo = (const float*)d_in[8]; const float* bo = (const float*)d_in[9];
    float* out = (float*)d_out;

    const int N = in_sizes[0] / D;
    const int E = in_sizes[1] / 2;

    float *q, *k, *v, *agg;
    int *deg;
    cudaGetSymbolAddress((void**)&q,   g_q);
    cudaGetSymbolAddress((void**)&k,   g_k);
    cudaGetSymbolAddress((void**)&v,   g_v);
    cudaGetSymbolAddress((void**)&agg, g_agg);
    cudaGetSymbolAddress((void**)&deg, g_deg);

    cudaMemsetAsync(deg, 0, (size_t)N * sizeof(int));

    const int gblocks = (N + 127) / 128;
    const int eb8     = (E + 2047) / 2048;   // 8 edges/thread, 256 threads

    k_gemm_deg    <<<gblocks + eb8, 256>>>(feats, Wq, bq, q, N, gblocks, ei, E);
    k_gemm_scan   <<<gblocks + 1,   256>>>(feats, Wk, bk, k, N, gblocks, N, E);
    k_gemm_scatter<<<gblocks + eb8, 256>>>(feats, Wv, bv, v, N, gblocks, ei, E);

    node_attn_kernel<<<(N + 7) / 8, 256>>>(N);

    gemm_bias_kernel<<<gblocks, 256>>>(agg, Wo, bo, out, N);
}